// round 1
// baseline (speedup 1.0000x reference)
#include <cuda_runtime.h>
#include <cstdint>

// Problem constants (fixed by the dataset)
#define BB_ 16
#define TT_ 8192
#define DD_ 192
#define KK_ 512
#define SPAN_ 8
#define SS_ 1024            // TT_/SPAN_
#define BS_ 16384           // BB_*SS_

// Output layout: q_out | loss | idx_out | boundaries (all float32)
#define Q_ELEMS (BB_*TT_*DD_)       // 25165824
#define LOSS_OFF (Q_ELEMS)
#define IDX_OFF  (Q_ELEMS + 1)
#define BND_OFF  (IDX_OFF + BB_*TT_)

// K2 tiling
#define TM_ 64              // segments per block
#define NT_ 128             // codes per smem tile
#define PSTR_ 130           // pooled smem row stride (floats), 64 segs duplicated = 128 + pad
#define CSTR_ 132           // codes smem row stride (floats), 128 + pad
#define K2_SMEM_BYTES ((DD_*PSTR_ + DD_*CSTR_ + NT_) * 4)

// Scratch (no allocation allowed -> __device__ globals)
__device__ float g_pooled[BS_*DD_];
__device__ float g_hnorm[KK_];
__device__ int   g_sidx[BS_];
__device__ float g_epart[BS_];
__device__ int   g_bcount;

#define FMA2(acc, a, b) \
    asm("fma.rn.f32x2 %0, %1, %2, %0;" : "+l"(acc) : "l"(a), "l"(b))

// ---------------------------------------------------------------------------
// K0: zero the boundary counter (everything else is fully overwritten)
// ---------------------------------------------------------------------------
__global__ void k0_init() {
    if (threadIdx.x == 0) g_bcount = 0;
}

// ---------------------------------------------------------------------------
// K1: fused boundary predictor + segment pooling.
// One block per segment (8 tokens x 192 dims = 6 KB read).
// Warp w handles token w: coalesced loads, stash to smem, dot with boundary_w.
// Then threads 0..191 pool across the 8 tokens.
// ---------------------------------------------------------------------------
__global__ void __launch_bounds__(256) k1_pool_boundary(
    const float* __restrict__ x,
    const float* __restrict__ bw,
    const float* __restrict__ bb,
    float* __restrict__ bnd_out)
{
    __shared__ float sx[SPAN_ * DD_];
    __shared__ int scnt;
    const int tid = threadIdx.x;
    const int w = tid >> 5, lane = tid & 31;
    const int s = blockIdx.x;
    const long base = (long)s * (SPAN_ * DD_);

    if (tid == 0) scnt = 0;
    __syncthreads();

    float lp = 0.f;
    #pragma unroll
    for (int k = 0; k < 6; k++) {
        int d = lane + 32 * k;
        float v = x[base + w * DD_ + d];
        sx[w * DD_ + d] = v;
        lp += v * bw[d];
    }
    #pragma unroll
    for (int m = 16; m > 0; m >>= 1) lp += __shfl_xor_sync(0xffffffffu, lp, m);
    if (lane == 0) {
        float logit = lp + bb[0];
        float flag = (logit > 0.f) ? 1.f : 0.f;   // sigmoid(l) > 0.5 <=> l > 0
        bnd_out[s * SPAN_ + w] = flag;
        if (flag > 0.f) atomicAdd(&scnt, 1);
    }
    __syncthreads();

    if (tid < DD_) {
        float acc = 0.f;
        #pragma unroll
        for (int t = 0; t < SPAN_; t++) acc += sx[t * DD_ + tid];
        g_pooled[(long)s * DD_ + tid] = acc * (1.0f / SPAN_);
    }
    if (tid == 0) atomicAdd(&g_bcount, scnt);
}

// ---------------------------------------------------------------------------
// K1b: half squared norms of codebook rows.
// ---------------------------------------------------------------------------
__global__ void k_hnorm(const float* __restrict__ cb)
{
    int k = blockIdx.x * blockDim.x + threadIdx.x;
    if (k < KK_) {
        const float* r = cb + (long)k * DD_;
        float s = 0.f;
        #pragma unroll 8
        for (int d = 0; d < DD_; d++) s += r[d] * r[d];
        g_hnorm[k] = 0.5f * s;
    }
}

// ---------------------------------------------------------------------------
// K2: VQ nearest-codebook search.
// argmin ||p - c||^2 == argmax (p.c - 0.5*||c||^2).
// Register-tiled GEMM with packed fp32x2 FMAs:
//   - pooled stored DUPLICATED in smem -> dup pair is a single LDS.64
//   - codes stored contiguously        -> code pair comes packed from LDS.128
// Block: 64 segments x all 512 codes (4 tiles of 128).
// Thread (cg=tid&15, sg=tid>>4): 4 segments x 8 codes = 16 f32x2 accumulators.
// Tie-break: ascending scan with strict '>' keeps the first (lowest) index,
// matching jnp.argmin.
// ---------------------------------------------------------------------------
extern __shared__ float smem2[];

__global__ void __launch_bounds__(256, 1) k2_vq(const float* __restrict__ cb)
{
    float* sP = smem2;                  // [DD_][PSTR_]  pooled, duplicated
    float* sC = sP + DD_ * PSTR_;       // [DD_][CSTR_]  code tile
    float* sH = sC + DD_ * CSTR_;       // [NT_]         half norms
    const int tid = threadIdx.x;
    const int cg = tid & 15;
    const int sg = tid >> 4;
    const int s0 = blockIdx.x * TM_;

    // Load pooled tile (transpose + duplicate). Coalesced global reads.
    for (int idx = tid; idx < TM_ * DD_; idx += 256) {
        int seg = idx / DD_, d = idx - seg * DD_;
        float v = g_pooled[(long)s0 * DD_ + idx];
        *(float2*)&sP[d * PSTR_ + 2 * seg] = make_float2(v, v);
    }

    unsigned long long acc[4][4];
    #pragma unroll
    for (int i = 0; i < 4; i++)
        #pragma unroll
        for (int j = 0; j < 4; j++) acc[i][j] = 0ull;

    float best[4]; int bidx[4];
    #pragma unroll
    for (int i = 0; i < 4; i++) { best[i] = -1e30f; bidx[i] = 0; }

    const float* pbase = sP + 2 * (sg * 4);
    const float* cbase = sC + cg * 8;

    for (int tile = 0; tile < KK_ / NT_; tile++) {
        const int c0 = tile * NT_;
        // Load code tile (transpose). Coalesced global reads.
        for (int idx = tid; idx < NT_ * DD_; idx += 256) {
            int c = idx / DD_, d = idx - c * DD_;
            sC[d * CSTR_ + c] = cb[(long)c0 * DD_ + idx];
        }
        if (tid < NT_) sH[tid] = g_hnorm[c0 + tid];
        __syncthreads();

        #pragma unroll 4
        for (int d = 0; d < DD_; d++) {
            unsigned long long p0 = *(const unsigned long long*)(pbase + d * PSTR_ + 0);
            unsigned long long p1 = *(const unsigned long long*)(pbase + d * PSTR_ + 2);
            unsigned long long p2 = *(const unsigned long long*)(pbase + d * PSTR_ + 4);
            unsigned long long p3 = *(const unsigned long long*)(pbase + d * PSTR_ + 6);
            ulonglong2 ca = *(const ulonglong2*)(cbase + d * CSTR_);
            ulonglong2 cc = *(const ulonglong2*)(cbase + d * CSTR_ + 4);
            FMA2(acc[0][0], p0, ca.x); FMA2(acc[0][1], p0, ca.y);
            FMA2(acc[0][2], p0, cc.x); FMA2(acc[0][3], p0, cc.y);
            FMA2(acc[1][0], p1, ca.x); FMA2(acc[1][1], p1, ca.y);
            FMA2(acc[1][2], p1, cc.x); FMA2(acc[1][3], p1, cc.y);
            FMA2(acc[2][0], p2, ca.x); FMA2(acc[2][1], p2, ca.y);
            FMA2(acc[2][2], p2, cc.x); FMA2(acc[2][3], p2, cc.y);
            FMA2(acc[3][0], p3, ca.x); FMA2(acc[3][1], p3, ca.y);
            FMA2(acc[3][2], p3, cc.x); FMA2(acc[3][3], p3, cc.y);
        }

        // Per-tile epilogue: scores = dot - 0.5||c||^2, running argmax.
        #pragma unroll
        for (int i = 0; i < 4; i++) {
            #pragma unroll
            for (int jj = 0; jj < 4; jj++) {
                unsigned long long v = acc[i][jj];
                float lo = __uint_as_float((unsigned)(v & 0xffffffffu));
                float hi = __uint_as_float((unsigned)(v >> 32));
                int cl = cg * 8 + 2 * jj;
                float slo = lo - sH[cl];
                float shi = hi - sH[cl + 1];
                int gl = c0 + cl;
                if (slo > best[i]) { best[i] = slo; bidx[i] = gl; }
                if (shi > best[i]) { best[i] = shi; bidx[i] = gl + 1; }
                acc[i][jj] = 0ull;
            }
        }
        __syncthreads();
    }

    // Reduce across the 16 code-groups (lanes 0..15 / 16..31 of each warp).
    #pragma unroll
    for (int i = 0; i < 4; i++) {
        float b = best[i]; int ix = bidx[i];
        #pragma unroll
        for (int m = 1; m < 16; m <<= 1) {
            float ob = __shfl_xor_sync(0xffffffffu, b, m);
            int   oi = __shfl_xor_sync(0xffffffffu, ix, m);
            if (ob > b || (ob == b && oi < ix)) { b = ob; ix = oi; }
        }
        if (cg == 0) g_sidx[s0 + sg * 4 + i] = ix;
    }
}

// ---------------------------------------------------------------------------
// K3: gather codebook row, STE output (pooled + (q - pooled), fp32 order
// matching the reference), broadcast to 8 tokens, per-segment e_latent partial,
// idx_out.
// ---------------------------------------------------------------------------
__global__ void __launch_bounds__(DD_) k3_expand(
    const float* __restrict__ cb, float* __restrict__ out)
{
    __shared__ float red[8];
    const int s = blockIdx.x;
    const int d = threadIdx.x;  // 0..191
    const int idx = g_sidx[s];
    const float c = cb[(long)idx * DD_ + d];
    const float p = g_pooled[(long)s * DD_ + d];
    const float q = p + (c - p);        // straight-through value, ref fp32 order
    const float diff = c - p;
    float e = diff * diff;
    #pragma unroll
    for (int m = 16; m > 0; m >>= 1) e += __shfl_xor_sync(0xffffffffu, e, m);
    if ((d & 31) == 0) red[d >> 5] = e;
    __syncthreads();
    if (d == 0) {
        float t = 0.f;
        #pragma unroll
        for (int i = 0; i < 6; i++) t += red[i];
        g_epart[s] = t;
    }
    const long qb = (long)s * SPAN_ * DD_;
    #pragma unroll
    for (int t = 0; t < SPAN_; t++) out[qb + t * DD_ + d] = q;
    if (d < SPAN_) out[IDX_OFF + s * SPAN_ + d] = (float)idx;
}

// ---------------------------------------------------------------------------
// K4: deterministic loss reduction + finalize.
// ---------------------------------------------------------------------------
__global__ void __launch_bounds__(256) k4_loss(float* __restrict__ out)
{
    __shared__ double rd[256];
    const int tid = threadIdx.x;
    double a = 0.0;
    for (int i = tid; i < BS_; i += 256) a += (double)g_epart[i];
    rd[tid] = a;
    __syncthreads();
    for (int step = 128; step > 0; step >>= 1) {
        if (tid < step) rd[tid] += rd[tid + step];
        __syncthreads();
    }
    if (tid == 0) {
        float e_mean = (float)(rd[0] / (double)((long)BS_ * DD_));
        float bm = (float)g_bcount / (float)(BB_ * TT_);
        float dbm = bm - (1.0f / SPAN_);
        out[LOSS_OFF] = 0.25f * e_mean + 0.01f * dbm * dbm;
    }
}

// ---------------------------------------------------------------------------
extern "C" void kernel_launch(void* const* d_in, const int* in_sizes, int n_in,
                              void* d_out, int out_size)
{
    const float* x  = (const float*)d_in[0];
    const float* cb = (const float*)d_in[1];
    const float* bw = (const float*)d_in[2];
    const float* bb = (const float*)d_in[3];
    float* out = (float*)d_out;
    (void)in_sizes; (void)n_in; (void)out_size;

    cudaFuncSetAttribute(k2_vq, cudaFuncAttributeMaxDynamicSharedMemorySize,
                         K2_SMEM_BYTES);

    k0_init<<<1, 32>>>();
    k1_pool_boundary<<<BS_, 256>>>(x, bw, bb, out + BND_OFF);
    k_hnorm<<<2, 256>>>(cb);
    k2_vq<<<BS_ / TM_, 256, K2_SMEM_BYTES>>>(cb);
    k3_expand<<<BS_, DD_>>>(cb, out);
    k4_loss<<<1, 256>>>(out);
}

// round 2
// speedup vs baseline: 1.1117x; 1.1117x over previous
#include <cuda_runtime.h>
#include <cstdint>

// Problem constants
#define BB_ 16
#define TT_ 8192
#define DD_ 192
#define KK_ 512
#define SPAN_ 8
#define SS_ 1024
#define BS_ 16384           // B*S segments
#define NTOK_ (BB_*TT_)     // 131072 tokens

// Output layout: q_out | loss | idx_out | boundaries (all float32)
#define Q_ELEMS (BB_*TT_*DD_)
#define LOSS_OFF (Q_ELEMS)
#define IDX_OFF  (Q_ELEMS + 1)
#define BND_OFF  (IDX_OFF + NTOK_)

// K2 tiling
#define TM_ 128             // segments per block -> grid 128, single wave
#define NT_ 64              // codes per chunk (128 dup slots)
#define NCHUNK_ (KK_/NT_)   // 8
#define RSTR_ 132           // smem row stride in floats (528B, 16B aligned)
#define K2_SMEM_BYTES (2 * DD_ * RSTR_ * 4)   // 202752 B

// Scratch
__device__ float g_pooled[BS_*DD_];     // [seg][d]  (for K3)
__device__ float g_pT[DD_*BS_];         // [d][seg]  (for K2)
__device__ float g_cbTd[DD_*2*KK_];     // [d][2c] duplicated-transposed codebook
__device__ float g_hnorm[KK_];
__device__ int   g_sidx[BS_];
__device__ float g_epart[BS_];
__device__ int   g_bcount;

#define FMA2(acc, a, b) \
    asm("fma.rn.f32x2 %0, %1, %2, %0;" : "+l"(acc) : "l"(a), "l"(b))

__device__ __forceinline__ unsigned smem_u32(const void* p) {
    unsigned a;
    asm("{ .reg .u64 t; cvta.to.shared.u64 t, %1; cvt.u32.u64 %0, t; }"
        : "=r"(a) : "l"(p));
    return a;
}
__device__ __forceinline__ void cp16(unsigned dst, const void* src) {
    asm volatile("cp.async.cg.shared.global [%0], [%1], 16;" :: "r"(dst), "l"(src));
}
__device__ __forceinline__ void cp_commit() {
    asm volatile("cp.async.commit_group;");
}
__device__ __forceinline__ void cp_wait0() {
    asm volatile("cp.async.wait_group 0;");
}

// ---------------------------------------------------------------------------
// Khn: codebook half norms + zero boundary counter.
// ---------------------------------------------------------------------------
__global__ void k_hnorm(const float* __restrict__ cb)
{
    int k = blockIdx.x * blockDim.x + threadIdx.x;
    if (k == 0) g_bcount = 0;
    if (k < KK_) {
        const float* r = cb + (long)k * DD_;
        float s = 0.f;
        #pragma unroll 8
        for (int d = 0; d < DD_; d++) s += r[d] * r[d];
        g_hnorm[k] = 0.5f * s;
    }
}

// ---------------------------------------------------------------------------
// Kcb: transpose + duplicate codebook: g_cbTd[d][2c] = g_cbTd[d][2c+1] = cb[c][d]
// Tiles of 32 codes x 32 d. grid = (512/32) x (192/32) = 96 blocks.
// ---------------------------------------------------------------------------
__global__ void __launch_bounds__(256) k_cbT(const float* __restrict__ cb)
{
    __shared__ float t[32 * 33];
    const int ct = blockIdx.x & 15;       // code tile
    const int dt = blockIdx.x >> 4;       // d tile
    const int tid = threadIdx.x;
    for (int i = tid; i < 1024; i += 256) {
        int c = i >> 5, d = i & 31;
        t[d * 33 + c] = cb[(long)(ct * 32 + c) * DD_ + dt * 32 + d];
    }
    __syncthreads();
    for (int i = tid; i < 1024; i += 256) {
        int d = i >> 5, c = i & 31;
        float v = t[d * 33 + c];
        *(float2*)&g_cbTd[(long)(dt * 32 + d) * (2 * KK_) + ct * 64 + 2 * c]
            = make_float2(v, v);
    }
}

// ---------------------------------------------------------------------------
// K1: boundary predictor + pooling. 512 blocks x 256 threads.
// Block = 32 segments = 256 tokens. d processed in 6 chunks of 32.
// Deterministic per-thread logit accumulation (thread <-> token).
// Writes pooled in both [seg][d] and [d][seg] layouts (coalesced).
// ---------------------------------------------------------------------------
__global__ void __launch_bounds__(256) k1_pool_boundary(
    const float* __restrict__ x,
    const float* __restrict__ bw,
    const float* __restrict__ bb,
    float* __restrict__ bnd_out)
{
    __shared__ float sx[256 * 33];     // [token][33] chunk of x
    __shared__ float pTc[32 * 33];     // [d][seg] pooled chunk staging
    const int tid = threadIdx.x;
    const long tok0 = (long)blockIdx.x * 256;
    const int s0 = blockIdx.x * 32;

    float logit = 0.f;

    #pragma unroll 1
    for (int dc = 0; dc < 6; dc++) {
        // load x chunk: 2048 float4
        for (int i = tid; i < 2048; i += 256) {
            int token = i >> 3, j4 = (i & 7) * 4;
            float4 v = *(const float4*)(x + (tok0 + token) * DD_ + dc * 32 + j4);
            float* p = &sx[token * 33 + j4];
            p[0] = v.x; p[1] = v.y; p[2] = v.z; p[3] = v.w;
        }
        __syncthreads();

        // boundary partial (thread = token tid)
        {
            const float* bwc = bw + dc * 32;
            const float* row = &sx[tid * 33];
            float l = 0.f;
            #pragma unroll 8
            for (int j = 0; j < 32; j++) l += row[j] * __ldg(&bwc[j]);
            logit += l;
        }

        // pooled chunk: 32 segs x 32 d = 1024 outputs, 4 per thread
        #pragma unroll
        for (int m = 0; m < 4; m++) {
            int o = tid + 256 * m;
            int seg = o >> 5, d = o & 31;
            float s = 0.f;
            #pragma unroll
            for (int t = 0; t < SPAN_; t++) s += sx[(seg * 8 + t) * 33 + d];
            s *= 0.125f;
            g_pooled[(long)(s0 + seg) * DD_ + dc * 32 + d] = s;
            pTc[d * 33 + seg] = s;
        }
        __syncthreads();

        // write transposed pooled rows (coalesced 128B per row)
        #pragma unroll
        for (int m = 0; m < 4; m++) {
            int i = tid + 256 * m;
            int d = i >> 5, sg = i & 31;
            g_pT[(long)(dc * 32 + d) * BS_ + s0 + sg] = pTc[d * 33 + sg];
        }
    }

    // boundary finalize
    float lg = logit + bb[0];
    float flag = (lg > 0.f) ? 1.f : 0.f;
    bnd_out[tok0 + tid] = flag;
    unsigned m = __ballot_sync(0xffffffffu, flag > 0.f);
    if ((tid & 31) == 0) atomicAdd(&g_bcount, __popc(m));
}

// ---------------------------------------------------------------------------
// K2: VQ argmax( p.c - 0.5||c||^2 ). grid=128 (single wave), 256 threads.
// smem: sP [192][132] pooled (seg pairs pack naturally),
//       sC [192][132] dup'd code chunk (64 codes -> 128 slots).
// Thread (ty=tid>>4, tx=tid&15): 8 segments (4 pairs) x 4 codes.
// Inner loop per d: 4x LDS.128 + 16x FMA2, zero pack instructions.
// cp.async chunk prefetch overlapped with register-only argmax epilogue.
// ---------------------------------------------------------------------------
extern __shared__ float smem2[];

__global__ void __launch_bounds__(256, 1) k2_vq()
{
    float* sP = smem2;
    float* sC = smem2 + DD_ * RSTR_;
    const unsigned sPu = smem_u32(sP);
    const unsigned sCu = smem_u32(sC);
    const int tid = threadIdx.x;
    const int ty = tid >> 4;      // seg group: segs ty*8 .. ty*8+7
    const int tx = tid & 15;      // code group: 4 codes
    const int s0 = blockIdx.x * TM_;

    // initial fills: pooled slab + chunk 0 (6144 granules each, 24/thread)
    for (int i = tid; i < 6144; i += 256) {
        int row = i >> 5, col = i & 31;
        cp16(sPu + (unsigned)(row * RSTR_ + col * 4) * 4,
             g_pT + (long)row * BS_ + s0 + col * 4);
    }
    for (int i = tid; i < 6144; i += 256) {
        int row = i >> 5, col = i & 31;
        cp16(sCu + (unsigned)(row * RSTR_ + col * 4) * 4,
             g_cbTd + (long)row * (2 * KK_) + col * 4);
    }
    cp_commit();
    cp_wait0();
    __syncthreads();

    unsigned long long acc[4][4];
    #pragma unroll
    for (int i = 0; i < 4; i++)
        #pragma unroll
        for (int j = 0; j < 4; j++) acc[i][j] = 0ull;

    float best[8]; int bidx[8];
    #pragma unroll
    for (int i = 0; i < 8; i++) { best[i] = -1e30f; bidx[i] = 0; }

    const float* pb = sP + ty * 8;
    const float* cb_ = sC + tx * 8;

    for (int chunk = 0; chunk < NCHUNK_; chunk++) {
        // -------- compute over full depth --------
        #pragma unroll 4
        for (int d = 0; d < DD_; d++) {
            ulonglong2 s01 = *(const ulonglong2*)(pb + d * RSTR_);
            ulonglong2 s23 = *(const ulonglong2*)(pb + d * RSTR_ + 4);
            ulonglong2 c01 = *(const ulonglong2*)(cb_ + d * RSTR_);
            ulonglong2 c23 = *(const ulonglong2*)(cb_ + d * RSTR_ + 4);
            FMA2(acc[0][0], s01.x, c01.x); FMA2(acc[0][1], s01.x, c01.y);
            FMA2(acc[0][2], s01.x, c23.x); FMA2(acc[0][3], s01.x, c23.y);
            FMA2(acc[1][0], s01.y, c01.x); FMA2(acc[1][1], s01.y, c01.y);
            FMA2(acc[1][2], s01.y, c23.x); FMA2(acc[1][3], s01.y, c23.y);
            FMA2(acc[2][0], s23.x, c01.x); FMA2(acc[2][1], s23.x, c01.y);
            FMA2(acc[2][2], s23.x, c23.x); FMA2(acc[2][3], s23.x, c23.y);
            FMA2(acc[3][0], s23.y, c01.x); FMA2(acc[3][1], s23.y, c01.y);
            FMA2(acc[3][2], s23.y, c23.x); FMA2(acc[3][3], s23.y, c23.y);
        }
        __syncthreads();   // all reads of sC done

        // prefetch next chunk while doing the register-only epilogue
        if (chunk < NCHUNK_ - 1) {
            int c0n = (chunk + 1) * NT_;
            for (int i = tid; i < 6144; i += 256) {
                int row = i >> 5, col = i & 31;
                cp16(sCu + (unsigned)(row * RSTR_ + col * 4) * 4,
                     g_cbTd + (long)row * (2 * KK_) + 2 * c0n + col * 4);
            }
            cp_commit();
        }

        // -------- epilogue: scores + running argmax --------
        const int cbase = chunk * NT_ + tx * 4;
        #pragma unroll
        for (int j = 0; j < 4; j++) {
            float hn = __ldg(&g_hnorm[cbase + j]);
            int gidx = cbase + j;
            #pragma unroll
            for (int i = 0; i < 4; i++) {
                unsigned long long v = acc[i][j];
                float lo = __uint_as_float((unsigned)(v & 0xffffffffu)) - hn;
                float hi = __uint_as_float((unsigned)(v >> 32)) - hn;
                if (lo > best[2 * i])     { best[2 * i] = lo;     bidx[2 * i] = gidx; }
                if (hi > best[2 * i + 1]) { best[2 * i + 1] = hi; bidx[2 * i + 1] = gidx; }
                acc[i][j] = 0ull;
            }
        }

        if (chunk < NCHUNK_ - 1) {
            cp_wait0();
            __syncthreads();
        }
    }

    // cross-tx reduce (tx = lane&15, same-ty threads are contiguous lanes)
    #pragma unroll
    for (int i = 0; i < 8; i++) {
        float b = best[i]; int ix = bidx[i];
        #pragma unroll
        for (int m = 1; m < 16; m <<= 1) {
            float ob = __shfl_xor_sync(0xffffffffu, b, m);
            int   oi = __shfl_xor_sync(0xffffffffu, ix, m);
            if (ob > b || (ob == b && oi < ix)) { b = ob; ix = oi; }
        }
        if (tx == 0) g_sidx[s0 + ty * 8 + i] = ix;
    }
}

// ---------------------------------------------------------------------------
// K3: gather + STE broadcast + per-segment e_latent partial + idx_out.
// ---------------------------------------------------------------------------
__global__ void __launch_bounds__(DD_) k3_expand(
    const float* __restrict__ cb, float* __restrict__ out)
{
    __shared__ float red[8];
    const int s = blockIdx.x;
    const int d = threadIdx.x;
    const int idx = g_sidx[s];
    const float c = cb[(long)idx * DD_ + d];
    const float p = g_pooled[(long)s * DD_ + d];
    const float q = p + (c - p);
    const float diff = c - p;
    float e = diff * diff;
    #pragma unroll
    for (int m = 16; m > 0; m >>= 1) e += __shfl_xor_sync(0xffffffffu, e, m);
    if ((d & 31) == 0) red[d >> 5] = e;
    __syncthreads();
    if (d == 0) {
        float t = 0.f;
        #pragma unroll
        for (int i = 0; i < 6; i++) t += red[i];
        g_epart[s] = t;
    }
    const long qb = (long)s * SPAN_ * DD_;
    #pragma unroll
    for (int t = 0; t < SPAN_; t++) out[qb + t * DD_ + d] = q;
    if (d < SPAN_) out[IDX_OFF + s * SPAN_ + d] = (float)idx;
}

// ---------------------------------------------------------------------------
// K4: deterministic loss reduction.
// ---------------------------------------------------------------------------
__global__ void __launch_bounds__(256) k4_loss(float* __restrict__ out)
{
    __shared__ double rd[256];
    const int tid = threadIdx.x;
    double a = 0.0;
    for (int i = tid; i < BS_; i += 256) a += (double)g_epart[i];
    rd[tid] = a;
    __syncthreads();
    for (int step = 128; step > 0; step >>= 1) {
        if (tid < step) rd[tid] += rd[tid + step];
        __syncthreads();
    }
    if (tid == 0) {
        float e_mean = (float)(rd[0] / (double)((long)BS_ * DD_));
        float bm = (float)g_bcount / (float)NTOK_;
        float dbm = bm - (1.0f / SPAN_);
        out[LOSS_OFF] = 0.25f * e_mean + 0.01f * dbm * dbm;
    }
}

// ---------------------------------------------------------------------------
extern "C" void kernel_launch(void* const* d_in, const int* in_sizes, int n_in,
                              void* d_out, int out_size)
{
    const float* x  = (const float*)d_in[0];
    const float* cb = (const float*)d_in[1];
    const float* bw = (const float*)d_in[2];
    const float* bb = (const float*)d_in[3];
    float* out = (float*)d_out;
    (void)in_sizes; (void)n_in; (void)out_size;

    cudaFuncSetAttribute(k2_vq, cudaFuncAttributeMaxDynamicSharedMemorySize,
                         K2_SMEM_BYTES);

    k_hnorm<<<2, 256>>>(cb);
    k_cbT<<<96, 256>>>(cb);
    k1_pool_boundary<<<NTOK_ / 256, 256>>>(x, bw, bb, out + BND_OFF);
    k2_vq<<<BS_ / TM_, 256, K2_SMEM_BYTES>>>();
    k3_expand<<<BS_, DD_>>>(cb, out);
    k4_loss<<<1, 256>>>(out);
}

// round 5
// speedup vs baseline: 1.5338x; 1.3797x over previous
#include <cuda_runtime.h>
#include <cstdint>

// Problem constants
#define BB_ 16
#define TT_ 8192
#define DD_ 192
#define KK_ 512
#define SPAN_ 8
#define BS_ 16384
#define NTOK_ (BB_*TT_)

// Output layout: q_out | loss | idx_out | boundaries (float32)
#define Q_ELEMS (BB_*TT_*DD_)
#define LOSS_OFF (Q_ELEMS)
#define IDX_OFF  (Q_ELEMS + 1)
#define BND_OFF  (IDX_OFF + NTOK_)

// K2 tiling: CTA = 128 segs x 512 codes, chunks of 64 codes
#define TM2_ 128
#define NCH_ 64                     // codes per chunk
#define CHUNKS_ (KK_/NCH_)          // 8
#define KSLABS_ (DD_/8)             // 24
#define A_FRAG_BYTES (TM2_*DD_*4)   // 98304
#define B_CHUNK_BYTES (NCH_*DD_*4)  // 49152
#define K2_DYN (A_FRAG_BYTES + 2*B_CHUNK_BYTES)   // 196608

// Scratch (__device__ globals; no allocation allowed)
__device__ __align__(16) float g_pooled[BS_*DD_];   // [seg][d] for K3
__device__ __align__(16) float g_pA[BS_*DD_];       // A-fragment order for K2
__device__ __align__(16) float g_cbF[KK_*DD_];      // B-fragment order codebook
__device__ float g_hnorm[KK_];
__device__ int   g_sidx[BS_];
__device__ float g_epart[BS_];
__device__ int   g_bcount;

// ---------------------------------------------------------------------------
// PTX helpers (sm_100 base-target safe: cp.async + mma.sync only)
// ---------------------------------------------------------------------------
__device__ __forceinline__ uint32_t smem_u32(const void* p) {
    uint32_t a;
    asm("{ .reg .u64 t; cvta.to.shared.u64 t, %1; cvt.u32.u64 %0, t; }"
        : "=r"(a) : "l"(p));
    return a;
}
__device__ __forceinline__ void cp16(uint32_t dst, const void* src) {
    asm volatile("cp.async.cg.shared.global [%0], [%1], 16;"
                 :: "r"(dst), "l"(src) : "memory");
}
__device__ __forceinline__ void cp_commit() {
    asm volatile("cp.async.commit_group;" ::: "memory");
}
__device__ __forceinline__ void cp_wait1() {
    asm volatile("cp.async.wait_group 1;" ::: "memory");
}
__device__ __forceinline__ void cp_wait0() {
    asm volatile("cp.async.wait_group 0;" ::: "memory");
}

__device__ __forceinline__ uint32_t tf32r(float x) {
    uint32_t u;
    asm("cvt.rna.tf32.f32 %0, %1;" : "=r"(u) : "f"(x));
    return u;
}
// D += A(16x8 tf32) * B(8x8 tf32), fp32 accumulate
__device__ __forceinline__ void mma8(float* c, const uint32_t* a,
                                     uint32_t b0, uint32_t b1) {
    asm volatile(
        "mma.sync.aligned.m16n8k8.row.col.f32.tf32.tf32.f32 "
        "{%0,%1,%2,%3}, {%4,%5,%6,%7}, {%8,%9}, {%0,%1,%2,%3};"
        : "+f"(c[0]), "+f"(c[1]), "+f"(c[2]), "+f"(c[3])
        : "r"(a[0]), "r"(a[1]), "r"(a[2]), "r"(a[3]), "r"(b0), "r"(b1));
}

// ---------------------------------------------------------------------------
// Khn: codebook half norms + zero boundary counter.
// ---------------------------------------------------------------------------
__global__ void k_hnorm(const float* __restrict__ cb)
{
    int k = blockIdx.x * blockDim.x + threadIdx.x;
    if (k == 0) g_bcount = 0;
    if (k < KK_) {
        const float* r = cb + (long)k * DD_;
        float s = 0.f;
        #pragma unroll 8
        for (int d = 0; d < DD_; d++) s += r[d] * r[d];
        g_hnorm[k] = 0.5f * s;
    }
}

// ---------------------------------------------------------------------------
// Kcbprep: codebook in B-fragment order (fp32; tf32 split done at use).
// g_cbF float2 index = ((chunk*8 + nt)*24 + ks)*32 + l, holding
// {cb[c][ks*8+tig], cb[c][ks*8+tig+4]} with c = chunk*64+nt*8+(l>>2), tig=l&3.
// ---------------------------------------------------------------------------
__global__ void __launch_bounds__(256) k_cbprep(const float* __restrict__ cb)
{
    int i = blockIdx.x * 256 + threadIdx.x;
    if (i >= KK_ * 24 * 4) return;
    int c = i / 96, rem = i - c * 96;
    int ks = rem >> 2, tig = rem & 3;
    int k0 = ks * 8 + tig;
    float v0 = cb[(long)c * DD_ + k0];
    float v1 = cb[(long)c * DD_ + k0 + 4];
    int chunk = c >> 6, nt = (c >> 3) & 7, l = ((c & 7) << 2) | tig;
    ((float2*)g_cbF)[((chunk * 8 + nt) * 24 + ks) * 32 + l] = make_float2(v0, v1);
}

// ---------------------------------------------------------------------------
// K1: boundary predictor + segment pooling.
// Writes pooled twice: plain [seg][d] (K3) and A-fragment order (K2).
// Fragment: row = mt*16 + (l>>2) + 8*(r&1), d = ks*8 + (l&3) + 4*(r>>1),
// float4 index b*6144 + (mt*24+ks)*32 + l, component r.
// ---------------------------------------------------------------------------
__global__ void __launch_bounds__(256) k1_pool_boundary(
    const float* __restrict__ x,
    const float* __restrict__ bw,
    const float* __restrict__ bb,
    float* __restrict__ bnd_out)
{
    __shared__ float sx[256 * 33];
    const int tid = threadIdx.x;
    const long tok0 = (long)blockIdx.x * 256;
    const int s0 = blockIdx.x * 32;

    float logit = 0.f;

    #pragma unroll 1
    for (int dc = 0; dc < 6; dc++) {
        for (int i = tid; i < 2048; i += 256) {
            int token = i >> 3, j4 = (i & 7) * 4;
            float4 v = *(const float4*)(x + (tok0 + token) * DD_ + dc * 32 + j4);
            float* p = &sx[token * 33 + j4];
            p[0] = v.x; p[1] = v.y; p[2] = v.z; p[3] = v.w;
        }
        __syncthreads();

        {
            const float* bwc = bw + dc * 32;
            const float* row = &sx[tid * 33];
            float l = 0.f;
            #pragma unroll 8
            for (int j = 0; j < 32; j++) l += row[j] * __ldg(&bwc[j]);
            logit += l;
        }

        // plain layout (for K3)
        #pragma unroll
        for (int m = 0; m < 4; m++) {
            int o = tid + 256 * m;
            int seg = o >> 5, d = o & 31;
            float s = 0.f;
            #pragma unroll
            for (int t = 0; t < SPAN_; t++) s += sx[(seg * 8 + t) * 33 + d];
            g_pooled[(long)(s0 + seg) * DD_ + dc * 32 + d] = s * 0.125f;
        }

        // A-fragment layout (for K2) — coalesced float4 store
        {
            const int mtl = tid >> 7;          // 0..1
            const int ksl = (tid >> 5) & 3;    // 0..3
            const int l = tid & 31;
            const int gid = l >> 2, tig = l & 3;
            float4 v;
            float* vv = &v.x;
            #pragma unroll
            for (int r = 0; r < 4; r++) {
                int segl = mtl * 16 + gid + 8 * (r & 1);
                int dl = ksl * 8 + tig + 4 * (r >> 1);
                float ssum = 0.f;
                #pragma unroll
                for (int t = 0; t < SPAN_; t++) ssum += sx[(segl * 8 + t) * 33 + dl];
                vv[r] = ssum * 0.125f;
            }
            int mt = (blockIdx.x * 2 + mtl) & 7;
            long b = blockIdx.x >> 2;
            ((float4*)g_pA)[b * 6144 + (mt * 24 + dc * 4 + ksl) * 32 + l] = v;
        }
        __syncthreads();
    }

    float lg = logit + bb[0];
    float flag = (lg > 0.f) ? 1.f : 0.f;
    bnd_out[tok0 + tid] = flag;
    unsigned m = __ballot_sync(0xffffffffu, flag > 0.f);
    if ((tid & 31) == 0) atomicAdd(&g_bcount, __popc(m));
}

// ---------------------------------------------------------------------------
// K2: 3xTF32 VQ search via mma.sync.m16n8k8.
// 8 warps = 4M x 2N; warp tile 32 segs x 32 codes/chunk.
// Cross-wx combine staged through shared memory (R4 bug fix: the two
// N-warps cover disjoint code halves for the SAME segments).
// ---------------------------------------------------------------------------
extern __shared__ __align__(1024) char k2smem[];

__global__ void __launch_bounds__(256, 1) k2_vq()
{
    __shared__ float s_hn[KK_];
    __shared__ float s_bv[2][TM2_];
    __shared__ int   s_bi[2][TM2_];

    const int tid = threadIdx.x;
    const int wid = tid >> 5, lane = tid & 31;
    const int wy = wid >> 1, wx = wid & 1;
    const int gid = lane >> 2, tig = lane & 3;
    const int s0 = blockIdx.x * TM2_;

    char* smA = k2smem;
    char* smB = k2smem + A_FRAG_BYTES;
    const uint32_t smA_u = smem_u32(smA);
    const uint32_t smB_u = smem_u32(smB);

    // prologue: A + B0 (group 0), B1 (group 1)
    {
        const char* srcA = (const char*)g_pA + (long)blockIdx.x * A_FRAG_BYTES;
        for (int i = tid; i < A_FRAG_BYTES / 16; i += 256)
            cp16(smA_u + (uint32_t)i * 16, srcA + (long)i * 16);
        const char* srcB0 = (const char*)g_cbF;
        for (int i = tid; i < B_CHUNK_BYTES / 16; i += 256)
            cp16(smB_u + (uint32_t)i * 16, srcB0 + (long)i * 16);
        cp_commit();
        const char* srcB1 = (const char*)g_cbF + B_CHUNK_BYTES;
        for (int i = tid; i < B_CHUNK_BYTES / 16; i += 256)
            cp16(smB_u + B_CHUNK_BYTES + (uint32_t)i * 16, srcB1 + (long)i * 16);
        cp_commit();
    }
    for (int i = tid; i < KK_; i += 256) s_hn[i] = g_hnorm[i];

    float best[4]; int bidx[4];
    #pragma unroll
    for (int i = 0; i < 4; i++) { best[i] = -3.0e38f; bidx[i] = 0; }

    float acc[2][4][4];
    #pragma unroll
    for (int mi = 0; mi < 2; mi++)
        #pragma unroll
        for (int ni = 0; ni < 4; ni++)
            #pragma unroll
            for (int j = 0; j < 4; j++) acc[mi][ni][j] = 0.f;

    for (int ch = 0; ch < CHUNKS_; ch++) {
        if (ch < CHUNKS_ - 1) cp_wait1(); else cp_wait0();
        __syncthreads();

        const char* bufB = smB + (ch & 1) * B_CHUNK_BYTES;

        #pragma unroll 2
        for (int ks = 0; ks < KSLABS_; ks++) {
            // A fragments: 2 m-tiles, fp32 -> hi/lo tf32 in regs
            uint32_t ah[2][4], al[2][4];
            #pragma unroll
            for (int mi = 0; mi < 2; mi++) {
                float4 av = *(const float4*)(smA +
                    ((long)((wy * 2 + mi) * 24 + ks) * 32 + lane) * 16);
                const float a4[4] = {av.x, av.y, av.z, av.w};
                #pragma unroll
                for (int j = 0; j < 4; j++) {
                    ah[mi][j] = tf32r(a4[j]);
                    al[mi][j] = tf32r(a4[j] - __uint_as_float(ah[mi][j]));
                }
            }
            // B fragments: 4 n-tiles
            #pragma unroll
            for (int ni = 0; ni < 4; ni++) {
                float2 bv = *(const float2*)(bufB +
                    ((long)((wx * 4 + ni) * 24 + ks) * 64 + lane * 2) * 4);
                uint32_t bh0 = tf32r(bv.x), bh1 = tf32r(bv.y);
                uint32_t bl0 = tf32r(bv.x - __uint_as_float(bh0));
                uint32_t bl1 = tf32r(bv.y - __uint_as_float(bh1));
                #pragma unroll
                for (int mi = 0; mi < 2; mi++) {
                    mma8(acc[mi][ni], ah[mi], bh0, bh1);
                    mma8(acc[mi][ni], ah[mi], bl0, bl1);
                    mma8(acc[mi][ni], al[mi], bh0, bh1);
                }
            }
        }
        __syncthreads();   // all reads of bufB done before overwrite

        // prefetch chunk ch+2 into buf (ch&1)
        if (ch < CHUNKS_ - 2) {
            const char* src = (const char*)g_cbF + (long)(ch + 2) * B_CHUNK_BYTES;
            uint32_t dst = smB_u + (uint32_t)(ch & 1) * B_CHUNK_BYTES;
            for (int i = tid; i < B_CHUNK_BYTES / 16; i += 256)
                cp16(dst + (uint32_t)i * 16, src + (long)i * 16);
            cp_commit();
        }

        // epilogue: scores + running argmax (codes ascending -> first-idx ties)
        #pragma unroll
        for (int ni = 0; ni < 4; ni++) {
            const int codeb = ch * NCH_ + (wx * 4 + ni) * 8 + 2 * tig;
            const float hn0 = s_hn[codeb], hn1 = s_hn[codeb + 1];
            #pragma unroll
            for (int mi = 0; mi < 2; mi++) {
                #pragma unroll
                for (int j = 0; j < 4; j++) {
                    float sc = acc[mi][ni][j] - ((j & 1) ? hn1 : hn0);
                    int slot = mi * 2 + (j >> 1);
                    int code = codeb + (j & 1);
                    if (sc > best[slot]) { best[slot] = sc; bidx[slot] = code; }
                    acc[mi][ni][j] = 0.f;
                }
            }
        }
    }

    // reduce over the 4 tig lanes (disjoint code classes mod 8)
    #pragma unroll
    for (int slot = 0; slot < 4; slot++) {
        float b = best[slot]; int ix = bidx[slot];
        #pragma unroll
        for (int m = 1; m <= 2; m <<= 1) {
            float ob = __shfl_xor_sync(0xffffffffu, b, m);
            int   oi = __shfl_xor_sync(0xffffffffu, ix, m);
            if (ob > b || (ob == b && oi < ix)) { b = ob; ix = oi; }
        }
        if (tig == 0) {
            int segl = wy * 32 + (slot >> 1) * 16 + gid + 8 * (slot & 1);
            s_bv[wx][segl] = b;
            s_bi[wx][segl] = ix;
        }
    }
    __syncthreads();

    // cross-wx combine (the two N-warps hold disjoint code halves)
    if (tid < TM2_) {
        float b0 = s_bv[0][tid], b1 = s_bv[1][tid];
        int   i0 = s_bi[0][tid], i1 = s_bi[1][tid];
        int take1 = (b1 > b0) || (b1 == b0 && i1 < i0);
        g_sidx[s0 + tid] = take1 ? i1 : i0;
    }
}

// ---------------------------------------------------------------------------
// K3: gather + STE broadcast (float4), per-segment e_latent partial, idx_out.
// ---------------------------------------------------------------------------
__global__ void __launch_bounds__(192) k3_expand(
    const float* __restrict__ cb, float* __restrict__ out)
{
    __shared__ float se[192];
    const int tid = threadIdx.x;
    const int sl = tid / 48, slot = tid - sl * 48;
    const int s = blockIdx.x * 4 + sl;
    const int idx = g_sidx[s];
    float4 c4 = *(const float4*)(cb + (long)idx * DD_ + slot * 4);
    float4 p4 = *(const float4*)(g_pooled + (long)s * DD_ + slot * 4);
    float4 q4;
    q4.x = p4.x + (c4.x - p4.x);
    q4.y = p4.y + (c4.y - p4.y);
    q4.z = p4.z + (c4.z - p4.z);
    q4.w = p4.w + (c4.w - p4.w);
    float dx = c4.x - p4.x, dy = c4.y - p4.y, dz = c4.z - p4.z, dw = c4.w - p4.w;
    se[tid] = dx * dx + dy * dy + dz * dz + dw * dw;
    __syncthreads();
    if (slot == 0) {
        float t = 0.f;
        #pragma unroll
        for (int j = 0; j < 48; j++) t += se[sl * 48 + j];
        g_epart[s] = t;
    }
    float4* qb = (float4*)out + (long)s * 384 + slot;
    #pragma unroll
    for (int tk = 0; tk < SPAN_; tk++) qb[tk * 48] = q4;
    if (slot < SPAN_) out[IDX_OFF + s * SPAN_ + slot] = (float)idx;
}

// ---------------------------------------------------------------------------
// K4: deterministic loss reduction.
// ---------------------------------------------------------------------------
__global__ void __launch_bounds__(256) k4_loss(float* __restrict__ out)
{
    __shared__ double rd[256];
    const int tid = threadIdx.x;
    double a = 0.0;
    for (int i = tid; i < BS_; i += 256) a += (double)g_epart[i];
    rd[tid] = a;
    __syncthreads();
    for (int step = 128; step > 0; step >>= 1) {
        if (tid < step) rd[tid] += rd[tid + step];
        __syncthreads();
    }
    if (tid == 0) {
        float e_mean = (float)(rd[0] / (double)((long)BS_ * DD_));
        float bm = (float)g_bcount / (float)NTOK_;
        float dbm = bm - (1.0f / SPAN_);
        out[LOSS_OFF] = 0.25f * e_mean + 0.01f * dbm * dbm;
    }
}

// ---------------------------------------------------------------------------
extern "C" void kernel_launch(void* const* d_in, const int* in_sizes, int n_in,
                              void* d_out, int out_size)
{
    const float* x  = (const float*)d_in[0];
    const float* cb = (const float*)d_in[1];
    const float* bw = (const float*)d_in[2];
    const float* bb = (const float*)d_in[3];
    float* out = (float*)d_out;
    (void)in_sizes; (void)n_in; (void)out_size;

    cudaFuncSetAttribute(k2_vq, cudaFuncAttributeMaxDynamicSharedMemorySize,
                         K2_DYN);

    k_hnorm<<<2, 256>>>(cb);
    k_cbprep<<<192, 256>>>(cb);
    k1_pool_boundary<<<NTOK_ / 256, 256>>>(x, bw, bb, out + BND_OFF);
    k2_vq<<<BS_ / TM2_, 256, K2_DYN>>>();
    k3_expand<<<BS_ / 4, 192>>>(cb, out);
    k4_loss<<<1, 256>>>(out);
}

// round 6
// speedup vs baseline: 1.9267x; 1.2561x over previous
#include <cuda_runtime.h>
#include <cstdint>

// Problem constants
#define BB_ 16
#define TT_ 8192
#define DD_ 192
#define KK_ 512
#define SPAN_ 8
#define BS_ 16384
#define NTOK_ (BB_*TT_)

// Output layout: q_out | loss | idx_out | boundaries (float32)
#define Q_ELEMS (BB_*TT_*DD_)
#define LOSS_OFF (Q_ELEMS)
#define IDX_OFF  (Q_ELEMS + 1)
#define BND_OFF  (IDX_OFF + NTOK_)

// K2: CTA = 128 segs x 512 codes; 16 chunks of 32 codes
#define TM2_ 128
#define NC_ 32
#define NCHUNK2_ 16
#define A_BYTES (TM2_*DD_*4)          // 98304
#define B_CHUNK_BYTES (NC_*DD_*8)     // 49152 (hi+lo fp32 packed)
#define K2_DYN (A_BYTES + 2*B_CHUNK_BYTES)   // 196608

// Scratch (__device__ globals; no allocation allowed)
__device__ __align__(16) float g_pooled[BS_*DD_];     // [seg][d] for K3
__device__ __align__(16) float g_pA[BS_*DD_];         // A-fragment order (raw fp32)
__device__ __align__(16) float g_cbF[KK_*DD_*2];      // B-fragment {h0,h1,l0,l1}
__device__ float g_hnorm[KK_];
__device__ int   g_sidx[BS_];
__device__ float g_epart[BS_];
__device__ int   g_bcount;

// ---------------------------------------------------------------------------
// PTX helpers (sm_100 base-target safe)
// ---------------------------------------------------------------------------
__device__ __forceinline__ uint32_t smem_u32(const void* p) {
    uint32_t a;
    asm("{ .reg .u64 t; cvta.to.shared.u64 t, %1; cvt.u32.u64 %0, t; }"
        : "=r"(a) : "l"(p));
    return a;
}
__device__ __forceinline__ void cp16(uint32_t dst, const void* src) {
    asm volatile("cp.async.cg.shared.global [%0], [%1], 16;"
                 :: "r"(dst), "l"(src) : "memory");
}
__device__ __forceinline__ void cp_commit() {
    asm volatile("cp.async.commit_group;" ::: "memory");
}
__device__ __forceinline__ void cp_wait1() {
    asm volatile("cp.async.wait_group 1;" ::: "memory");
}
__device__ __forceinline__ void cp_wait0() {
    asm volatile("cp.async.wait_group 0;" ::: "memory");
}
__device__ __forceinline__ uint32_t tf32r(float x) {
    uint32_t u;
    asm("cvt.rna.tf32.f32 %0, %1;" : "=r"(u) : "f"(x));
    return u;
}
// D += A(16x8 tf32) * B(8x8 tf32), fp32 accumulate
__device__ __forceinline__ void mma8(float* c, const uint32_t* a,
                                     uint32_t b0, uint32_t b1) {
    asm volatile(
        "mma.sync.aligned.m16n8k8.row.col.f32.tf32.tf32.f32 "
        "{%0,%1,%2,%3}, {%4,%5,%6,%7}, {%8,%9}, {%0,%1,%2,%3};"
        : "+f"(c[0]), "+f"(c[1]), "+f"(c[2]), "+f"(c[3])
        : "r"(a[0]), "r"(a[1]), "r"(a[2]), "r"(a[3]), "r"(b0), "r"(b1));
}

// ---------------------------------------------------------------------------
// Khn: coalesced codebook half norms (warp per code) + zero boundary counter.
// ---------------------------------------------------------------------------
__global__ void __launch_bounds__(256) k_hnorm(const float* __restrict__ cb)
{
    const int w = blockIdx.x * 8 + (threadIdx.x >> 5);
    const int lane = threadIdx.x & 31;
    if (blockIdx.x == 0 && threadIdx.x == 0) g_bcount = 0;
    float s = 0.f;
    #pragma unroll
    for (int j = 0; j < 6; j++) {
        float v = cb[(long)w * DD_ + lane + 32 * j];
        s += v * v;
    }
    #pragma unroll
    for (int m = 16; m > 0; m >>= 1) s += __shfl_xor_sync(0xffffffffu, s, m);
    if (lane == 0) g_hnorm[w] = 0.5f * s;
}

// ---------------------------------------------------------------------------
// Kcbprep: codebook -> B-fragment order, pre-split hi/lo.
// float4 index (ntc*24 + ks)*32 + l = {hi0, hi1, lo0, lo1} where
// ntc = ch*4 + nt, code c = ntc*8 + (l>>2), k0 = ks*8 + (l&3), k1 = k0+4.
// hi = rna-tf32(v); lo = v - hi (exact; tf32 mma truncates low bits on read).
// ---------------------------------------------------------------------------
__global__ void __launch_bounds__(256) k_cbprep(const float* __restrict__ cb)
{
    int i = blockIdx.x * 256 + threadIdx.x;    // 49152 total
    int l = i & 31;
    int ks = (i >> 5) % 24;
    int ntc = i / 768;                          // 0..63
    int c = ntc * 8 + (l >> 2);
    int k0 = ks * 8 + (l & 3);
    float v0 = cb[(long)c * DD_ + k0];
    float v1 = cb[(long)c * DD_ + k0 + 4];
    float h0 = __uint_as_float(tf32r(v0));
    float h1 = __uint_as_float(tf32r(v1));
    ((float4*)g_cbF)[(long)(ntc * 24 + ks) * 32 + l] =
        make_float4(h0, h1, v0 - h0, v1 - h1);
}

// ---------------------------------------------------------------------------
// K1: boundary predictor + segment pooling.
// bw cached in smem (kills the per-thread LDG storm); pooled staged in pTc
// so the A-fragment pass reads 4 LDS instead of re-pooling (64 LDS).
// ---------------------------------------------------------------------------
__global__ void __launch_bounds__(256) k1_pool_boundary(
    const float* __restrict__ x,
    const float* __restrict__ bw,
    const float* __restrict__ bb,
    float* __restrict__ bnd_out)
{
    __shared__ float sx[256 * 33];
    __shared__ float pTc[32 * 33];     // [seg_local][d_local] pooled chunk
    __shared__ float s_bw[DD_];
    const int tid = threadIdx.x;
    const long tok0 = (long)blockIdx.x * 256;
    const int s0 = blockIdx.x * 32;

    if (tid < DD_) s_bw[tid] = bw[tid];

    float logit = 0.f;

    #pragma unroll 1
    for (int dc = 0; dc < 6; dc++) {
        for (int i = tid; i < 2048; i += 256) {
            int token = i >> 3, j4 = (i & 7) * 4;
            float4 v = *(const float4*)(x + (tok0 + token) * DD_ + dc * 32 + j4);
            float* p = &sx[token * 33 + j4];
            p[0] = v.x; p[1] = v.y; p[2] = v.z; p[3] = v.w;
        }
        __syncthreads();

        {
            const float* row = &sx[tid * 33];
            const float* bwc = &s_bw[dc * 32];
            float l = 0.f;
            #pragma unroll 8
            for (int j = 0; j < 32; j++) l += row[j] * bwc[j];
            logit += l;
        }

        // pooled: 32 segs x 32 d, 4 outputs per thread
        #pragma unroll
        for (int m = 0; m < 4; m++) {
            int o = tid + 256 * m;
            int seg = o >> 5, d = o & 31;
            float s = 0.f;
            #pragma unroll
            for (int t = 0; t < SPAN_; t++) s += sx[(seg * 8 + t) * 33 + d];
            s *= 0.125f;
            g_pooled[(long)(s0 + seg) * DD_ + dc * 32 + d] = s;
            pTc[seg * 33 + d] = s;
        }
        __syncthreads();

        // A-fragment (raw fp32) from staged pooled values
        {
            const int wtl = tid >> 7;           // 0..1 warp-tile
            const int ksl = (tid >> 5) & 3;     // 0..3 k-slab within chunk
            const int l = tid & 31;
            const int gid = l >> 2, tig = l & 3;
            float4 v;
            float* vv = &v.x;
            #pragma unroll
            for (int r = 0; r < 4; r++) {
                int segl = wtl * 16 + gid + 8 * (r & 1);
                int dl = ksl * 8 + tig + 4 * (r >> 1);
                vv[r] = pTc[segl * 33 + dl];
            }
            int wgt = (blockIdx.x & 3) * 2 + wtl;
            long b = blockIdx.x >> 2;
            ((float4*)g_pA)[((b * 8 + wgt) * 24 + dc * 4 + ksl) * 32 + l] = v;
        }
        __syncthreads();
    }

    float lg = logit + bb[0];
    float flag = (lg > 0.f) ? 1.f : 0.f;
    bnd_out[tok0 + tid] = flag;
    unsigned m = __ballot_sync(0xffffffffu, flag > 0.f);
    if ((tid & 31) == 0) atomicAdd(&g_bcount, __popc(m));
}

// ---------------------------------------------------------------------------
// K2: 3xTF32 VQ search. 8 warps = 4M x 2N; per warp 2 m-tiles x 2 n-tiles.
// A raw fp32 in smem (split in regs: cvt hi, exact-sub lo, HW truncation);
// B pre-split hi/lo streamed via cp.async (zero in-loop B alu).
// ---------------------------------------------------------------------------
extern __shared__ __align__(1024) char k2smem[];

__global__ void __launch_bounds__(256, 1) k2_vq()
{
    __shared__ float s_hn[KK_];
    __shared__ float s_bv[2][TM2_];
    __shared__ int   s_bi[2][TM2_];

    const int tid = threadIdx.x;
    const int wid = tid >> 5, lane = tid & 31;
    const int wy = wid >> 1, wx = wid & 1;
    const int gid = lane >> 2, tig = lane & 3;
    const int s0 = blockIdx.x * TM2_;

    char* smA = k2smem;
    char* smB = k2smem + A_BYTES;
    const uint32_t smA_u = smem_u32(smA);
    const uint32_t smB_u = smem_u32(smB);

    // prologue: A + B chunk0 (group 0), B chunk1 (group 1)
    {
        const char* srcA = (const char*)g_pA + (long)blockIdx.x * A_BYTES;
        for (int i = tid; i < A_BYTES / 16; i += 256)
            cp16(smA_u + (uint32_t)i * 16, srcA + (long)i * 16);
        for (int i = tid; i < B_CHUNK_BYTES / 16; i += 256)
            cp16(smB_u + (uint32_t)i * 16, (const char*)g_cbF + (long)i * 16);
        cp_commit();
        for (int i = tid; i < B_CHUNK_BYTES / 16; i += 256)
            cp16(smB_u + B_CHUNK_BYTES + (uint32_t)i * 16,
                 (const char*)g_cbF + B_CHUNK_BYTES + (long)i * 16);
        cp_commit();
    }
    for (int i = tid; i < KK_; i += 256) s_hn[i] = g_hnorm[i];

    float best[4]; int bidx[4];
    #pragma unroll
    for (int i = 0; i < 4; i++) { best[i] = -3.0e38f; bidx[i] = 0; }

    float acc[2][2][4];
    #pragma unroll
    for (int mi = 0; mi < 2; mi++)
        #pragma unroll
        for (int ni = 0; ni < 2; ni++)
            #pragma unroll
            for (int j = 0; j < 4; j++) acc[mi][ni][j] = 0.f;

    const char* aBase0 = smA + ((long)((wy * 2 + 0) * 24) * 32 + lane) * 16;
    const char* aBase1 = smA + ((long)((wy * 2 + 1) * 24) * 32 + lane) * 16;

    for (int ch = 0; ch < NCHUNK2_; ch++) {
        if (ch < NCHUNK2_ - 1) cp_wait1(); else cp_wait0();
        __syncthreads();

        const char* bufB = smB + (ch & 1) * B_CHUNK_BYTES;
        const char* bBase0 = bufB + ((long)((wx * 2 + 0) * 24) * 32 + lane) * 16;
        const char* bBase1 = bufB + ((long)((wx * 2 + 1) * 24) * 32 + lane) * 16;

        #pragma unroll 4
        for (int ks = 0; ks < 24; ks++) {
            float4 a0 = *(const float4*)(aBase0 + ks * 512);
            float4 a1 = *(const float4*)(aBase1 + ks * 512);
            uint32_t ah0[4], ah1[4], al0[4], al1[4];
            const float a0v[4] = {a0.x, a0.y, a0.z, a0.w};
            const float a1v[4] = {a1.x, a1.y, a1.z, a1.w};
            #pragma unroll
            for (int j = 0; j < 4; j++) {
                ah0[j] = tf32r(a0v[j]);
                al0[j] = __float_as_uint(a0v[j] - __uint_as_float(ah0[j]));
                ah1[j] = tf32r(a1v[j]);
                al1[j] = __float_as_uint(a1v[j] - __uint_as_float(ah1[j]));
            }
            float4 b0 = *(const float4*)(bBase0 + ks * 512);   // {h0,h1,l0,l1}
            float4 b1 = *(const float4*)(bBase1 + ks * 512);
            uint32_t b0h0 = __float_as_uint(b0.x), b0h1 = __float_as_uint(b0.y);
            uint32_t b0l0 = __float_as_uint(b0.z), b0l1 = __float_as_uint(b0.w);
            uint32_t b1h0 = __float_as_uint(b1.x), b1h1 = __float_as_uint(b1.y);
            uint32_t b1l0 = __float_as_uint(b1.z), b1l1 = __float_as_uint(b1.w);

            mma8(acc[0][0], ah0, b0h0, b0h1);
            mma8(acc[0][0], ah0, b0l0, b0l1);
            mma8(acc[0][0], al0, b0h0, b0h1);
            mma8(acc[0][1], ah0, b1h0, b1h1);
            mma8(acc[0][1], ah0, b1l0, b1l1);
            mma8(acc[0][1], al0, b1h0, b1h1);
            mma8(acc[1][0], ah1, b0h0, b0h1);
            mma8(acc[1][0], ah1, b0l0, b0l1);
            mma8(acc[1][0], al1, b0h0, b0h1);
            mma8(acc[1][1], ah1, b1h0, b1h1);
            mma8(acc[1][1], ah1, b1l0, b1l1);
            mma8(acc[1][1], al1, b1h0, b1h1);
        }
        __syncthreads();   // all reads of bufB done before overwrite

        if (ch < NCHUNK2_ - 2) {
            const char* src = (const char*)g_cbF + (long)(ch + 2) * B_CHUNK_BYTES;
            uint32_t dst = smB_u + (uint32_t)(ch & 1) * B_CHUNK_BYTES;
            for (int i = tid; i < B_CHUNK_BYTES / 16; i += 256)
                cp16(dst + (uint32_t)i * 16, src + (long)i * 16);
            cp_commit();
        }

        // scores + running argmax (codes ascending -> first-index ties)
        #pragma unroll
        for (int ni = 0; ni < 2; ni++) {
            const int codeb = ch * NC_ + (wx * 2 + ni) * 8 + 2 * tig;
            const float hn0 = s_hn[codeb], hn1 = s_hn[codeb + 1];
            #pragma unroll
            for (int mi = 0; mi < 2; mi++) {
                #pragma unroll
                for (int j = 0; j < 4; j++) {
                    float sc = acc[mi][ni][j] - ((j & 1) ? hn1 : hn0);
                    int slot = mi * 2 + (j >> 1);
                    int code = codeb + (j & 1);
                    if (sc > best[slot]) { best[slot] = sc; bidx[slot] = code; }
                    acc[mi][ni][j] = 0.f;
                }
            }
        }
    }

    // reduce over the 4 tig lanes (disjoint code classes mod 8)
    #pragma unroll
    for (int slot = 0; slot < 4; slot++) {
        float b = best[slot]; int ix = bidx[slot];
        #pragma unroll
        for (int m = 1; m <= 2; m <<= 1) {
            float ob = __shfl_xor_sync(0xffffffffu, b, m);
            int   oi = __shfl_xor_sync(0xffffffffu, ix, m);
            if (ob > b || (ob == b && oi < ix)) { b = ob; ix = oi; }
        }
        if (tig == 0) {
            int segl = wy * 32 + (slot >> 1) * 16 + gid + 8 * (slot & 1);
            s_bv[wx][segl] = b;
            s_bi[wx][segl] = ix;
        }
    }
    __syncthreads();

    // cross-wx combine (the two N-warps hold disjoint code halves)
    if (tid < TM2_) {
        float b0 = s_bv[0][tid], b1 = s_bv[1][tid];
        int   i0 = s_bi[0][tid], i1 = s_bi[1][tid];
        int take1 = (b1 > b0) || (b1 == b0 && i1 < i0);
        g_sidx[s0 + tid] = take1 ? i1 : i0;
    }
}

// ---------------------------------------------------------------------------
// K3: gather + STE broadcast (float4), per-segment e_latent partial, idx_out.
// ---------------------------------------------------------------------------
__global__ void __launch_bounds__(192) k3_expand(
    const float* __restrict__ cb, float* __restrict__ out)
{
    __shared__ float se[192];
    const int tid = threadIdx.x;
    const int sl = tid / 48, slot = tid - sl * 48;
    const int s = blockIdx.x * 4 + sl;
    const int idx = g_sidx[s];
    float4 c4 = *(const float4*)(cb + (long)idx * DD_ + slot * 4);
    float4 p4 = *(const float4*)(g_pooled + (long)s * DD_ + slot * 4);
    float4 q4;
    q4.x = p4.x + (c4.x - p4.x);
    q4.y = p4.y + (c4.y - p4.y);
    q4.z = p4.z + (c4.z - p4.z);
    q4.w = p4.w + (c4.w - p4.w);
    float dx = c4.x - p4.x, dy = c4.y - p4.y, dz = c4.z - p4.z, dw = c4.w - p4.w;
    se[tid] = dx * dx + dy * dy + dz * dz + dw * dw;
    __syncthreads();
    if (slot == 0) {
        float t = 0.f;
        #pragma unroll
        for (int j = 0; j < 48; j++) t += se[sl * 48 + j];
        g_epart[s] = t;
    }
    float4* qb = (float4*)out + (long)s * 384 + slot;
    #pragma unroll
    for (int tk = 0; tk < SPAN_; tk++) qb[tk * 48] = q4;
    if (slot < SPAN_) out[IDX_OFF + s * SPAN_ + slot] = (float)idx;
}

// ---------------------------------------------------------------------------
// K4: deterministic loss reduction.
// ---------------------------------------------------------------------------
__global__ void __launch_bounds__(256) k4_loss(float* __restrict__ out)
{
    __shared__ double rd[256];
    const int tid = threadIdx.x;
    double a = 0.0;
    for (int i = tid; i < BS_; i += 256) a += (double)g_epart[i];
    rd[tid] = a;
    __syncthreads();
    for (int step = 128; step > 0; step >>= 1) {
        if (tid < step) rd[tid] += rd[tid + step];
        __syncthreads();
    }
    if (tid == 0) {
        float e_mean = (float)(rd[0] / (double)((long)BS_ * DD_));
        float bm = (float)g_bcount / (float)NTOK_;
        float dbm = bm - (1.0f / SPAN_);
        out[LOSS_OFF] = 0.25f * e_mean + 0.01f * dbm * dbm;
    }
}

// ---------------------------------------------------------------------------
extern "C" void kernel_launch(void* const* d_in, const int* in_sizes, int n_in,
                              void* d_out, int out_size)
{
    const float* x  = (const float*)d_in[0];
    const float* cb = (const float*)d_in[1];
    const float* bw = (const float*)d_in[2];
    const float* bb = (const float*)d_in[3];
    float* out = (float*)d_out;
    (void)in_sizes; (void)n_in; (void)out_size;

    cudaFuncSetAttribute(k2_vq, cudaFuncAttributeMaxDynamicSharedMemorySize,
                         K2_DYN);

    k_hnorm<<<64, 256>>>(cb);
    k_cbprep<<<192, 256>>>(cb);
    k1_pool_boundary<<<NTOK_ / 256, 256>>>(x, bw, bb, out + BND_OFF);
    k2_vq<<<BS_ / TM2_, 256, K2_DYN>>>();
    k3_expand<<<BS_ / 4, 192>>>(cb, out);
    k4_loss<<<1, 256>>>(out);
}